// round 5
// baseline (speedup 1.0000x reference)
#include <cuda_runtime.h>
#include <math.h>

#define NSQ    64
#define EPS_F  1e-6f
#define EPS2_F (1e-6f * 1e-6f)
#define TRUNC  0.1f
#define MAXP   262144
#define NCELL  32768   // 15-bit morton, 5 bits/axis

// 6 float4 per prim:
// q0 = {r00,r01,r02, tbx}   (tb = R^T t)
// q1 = {r10,r11,r12, tby}
// q2 = {r20,r21,r22, tbz}
// q3 = {isx2,isy2,isz2, 1/e2}
// q4 = {1/e1, e2/e1, -e1/2, pad}
// q5 = {tx, ty, tz, (TRUNC+Rmax)^2}
#define PQ 6

__device__ float4       g_sorted[MAXP];
__device__ unsigned int g_hist[NCELL];
__device__ unsigned int g_cursor[NCELL];

__device__ __forceinline__ float fast_lg2(float x) {
    float r; asm("lg2.approx.f32 %0, %1;" : "=f"(r) : "f"(x)); return r;
}
__device__ __forceinline__ float fast_ex2(float x) {
    float r; asm("ex2.approx.f32 %0, %1;" : "=f"(r) : "f"(x)); return r;
}
__device__ __forceinline__ float fast_rcp(float x) {
    float r; asm("rcp.approx.f32 %0, %1;" : "=f"(r) : "f"(x)); return r;
}
__device__ __forceinline__ float fast_sqrt(float x) {
    float r; asm("sqrt.approx.f32 %0, %1;" : "=f"(r) : "f"(x)); return r;
}

__device__ __forceinline__ unsigned part1by2(unsigned v) {
    v &= 0x3ff;
    v = (v | (v << 16)) & 0x030000FF;
    v = (v | (v << 8))  & 0x0300F00F;
    v = (v | (v << 4))  & 0x030C30C3;
    v = (v | (v << 2))  & 0x09249249;
    return v;
}
__device__ __forceinline__ unsigned cell_of(float x, float y, float z) {
    int ix = (int)floorf((x + 4.0f) * 4.0f);
    int iy = (int)floorf((y + 4.0f) * 4.0f);
    int iz = (int)floorf((z + 4.0f) * 4.0f);
    ix = ix < 0 ? 0 : (ix > 31 ? 31 : ix);
    iy = iy < 0 ? 0 : (iy > 31 ? 31 : iy);
    iz = iz < 0 ? 0 : (iz > 31 ? 31 : iz);
    return part1by2((unsigned)ix) | (part1by2((unsigned)iy) << 1) | (part1by2((unsigned)iz) << 2);
}

__global__ void k_zero() {
    int i = blockIdx.x * blockDim.x + threadIdx.x;
    if (i < NCELL) { g_hist[i] = 0; g_cursor[i] = 0; }
}

__global__ void k_count(const float* __restrict__ points, int P) {
    int p = blockIdx.x * blockDim.x + threadIdx.x;
    if (p >= P) return;
    unsigned c = cell_of(points[3*p+0], points[3*p+1], points[3*p+2]);
    atomicAdd(&g_hist[c], 1u);
}

__global__ void k_scan() {   // single block, 1024 threads, 32 cells each
    __shared__ unsigned ssum[1024];
    const int t = threadIdx.x;
    const int base = t * 32;
    unsigned run = 0;
    for (int j = 0; j < 32; j++) run += g_hist[base + j];
    ssum[t] = run;
    __syncthreads();
    for (int off = 1; off < 1024; off <<= 1) {
        unsigned v = (t >= off) ? ssum[t - off] : 0u;
        __syncthreads();
        ssum[t] += v;
        __syncthreads();
    }
    unsigned prefix = (t == 0) ? 0u : ssum[t - 1];
    for (int j = 0; j < 32; j++) {
        unsigned tmp = g_hist[base + j];
        g_hist[base + j] = prefix;
        prefix += tmp;
    }
}

__global__ void k_scatter(const float* __restrict__ points, int P) {
    int p = blockIdx.x * blockDim.x + threadIdx.x;
    if (p >= P) return;
    float x = points[3*p+0], y = points[3*p+1], z = points[3*p+2];
    unsigned c   = cell_of(x, y, z);
    unsigned pos = g_hist[c] + atomicAdd(&g_cursor[c], 1u);
    g_sorted[pos] = make_float4(x, y, z, __uint_as_float((unsigned)p));
}

__global__ void __launch_bounds__(256, 5)
superq_kernel(const float* __restrict__ raw_scale,
              const float* __restrict__ raw_exp,
              const float* __restrict__ raw_rot,
              const float* __restrict__ trans,
              float* __restrict__ out,               // [P] sdf ; [P,3] normals
              int P)
{
    __shared__ float4 sp[NSQ * PQ];
    const int tid = threadIdx.x;

    if (tid < NSQ) {
        const int i = tid;
        float qw = raw_rot[4*i+0], qx = raw_rot[4*i+1];
        float qy = raw_rot[4*i+2], qz = raw_rot[4*i+3];
        float qn = 1.0f / sqrtf(qw*qw + qx*qx + qy*qy + qz*qz);
        qw *= qn; qx *= qn; qy *= qn; qz *= qn;
        const float r00 = 1.0f - 2.0f*(qy*qy + qz*qz);
        const float r01 = 2.0f*(qx*qy - qw*qz);
        const float r02 = 2.0f*(qx*qz + qw*qy);
        const float r10 = 2.0f*(qx*qy + qw*qz);
        const float r11 = 1.0f - 2.0f*(qx*qx + qz*qz);
        const float r12 = 2.0f*(qy*qz - qw*qx);
        const float r20 = 2.0f*(qx*qz - qw*qy);
        const float r21 = 2.0f*(qy*qz + qw*qx);
        const float r22 = 1.0f - 2.0f*(qx*qx + qy*qy);
        const float tx = trans[3*i+0], ty = trans[3*i+1], tz = trans[3*i+2];
        const float tbx = r00*tx + r10*ty + r20*tz;
        const float tby = r01*tx + r11*ty + r21*tz;
        const float tbz = r02*tx + r12*ty + r22*tz;
        const float sx = expf(raw_scale[3*i+0]);
        const float sy = expf(raw_scale[3*i+1]);
        const float sz = expf(raw_scale[3*i+2]);
        const float e1 = 0.1f + 1.8f / (1.0f + expf(-raw_exp[2*i+0]));
        const float e2 = 0.1f + 1.8f / (1.0f + expf(-raw_exp[2*i+1]));
        const float Rmax = sqrtf(sx*sx + sy*sy + sz*sz);
        const float th   = TRUNC + Rmax;
        sp[i*PQ+0] = make_float4(r00, r01, r02, tbx);
        sp[i*PQ+1] = make_float4(r10, r11, r12, tby);
        sp[i*PQ+2] = make_float4(r20, r21, r22, tbz);
        sp[i*PQ+3] = make_float4(1.0f/(sx*sx), 1.0f/(sy*sy), 1.0f/(sz*sz), 1.0f/e2);
        sp[i*PQ+4] = make_float4(1.0f/e1, e2/e1, -0.5f*e1, 0.0f);
        sp[i*PQ+5] = make_float4(tx, ty, tz, th*th);
    }
    __syncthreads();

    const int p  = blockIdx.x * blockDim.x + tid;
    const int pc = p < P ? p : (P - 1);

    const float4 pt = g_sorted[pc];
    const float px = pt.x, py = pt.y, pz = pt.z;
    const unsigned orig = __float_as_uint(pt.w);

    float best = 3.0e38f;
    int   bi   = 0;

    // ---- Pass 1: sdf-only argmin with far-prim pruning ----
#pragma unroll 2
    for (int i = 0; i < NSQ; i++) {
        const float4 q5 = sp[i*PQ+5];
        const float ddx = px - q5.x, ddy = py - q5.y, ddz = pz - q5.z;
        const float d2  = ddx*ddx + ddy*ddy + ddz*ddz;
        const bool nearL = d2 < q5.w;                       // inside pruning ball?
        const unsigned nm = __ballot_sync(0xffffffffu, nearL);

        if (nm == 0u) {
            // every lane provably has s > TRUNC -> clamped value exactly 0.1
            const bool upd = TRUNC < best;
            best = upd ? TRUNC : best;
            bi   = upd ? i : bi;
        } else {
            const float4 q0 = sp[i*PQ+0];
            const float4 q1 = sp[i*PQ+1];
            const float4 q2 = sp[i*PQ+2];
            const float4 q3 = sp[i*PQ+3];
            const float4 q4 = sp[i*PQ+4];

            const float xc = q0.x*px + q1.x*py + q2.x*pz - q0.w;
            const float yc = q0.y*px + q1.y*py + q2.y*pz - q1.w;
            const float zc = q0.z*px + q1.z*py + q2.z*pz - q2.w;

            const float x2 = fmaxf(xc*xc, EPS2_F);
            const float y2 = fmaxf(yc*yc, EPS2_F);
            const float z2 = fmaxf(zc*zc, EPS2_F);

            const float r2 = x2 + y2 + z2;
            const float r0 = fast_sqrt(r2);

            const float t1 = fast_ex2(q3.w * fast_lg2(x2 * q3.x));
            const float t2 = fast_ex2(q3.w * fast_lg2(y2 * q3.y));
            const float t3 = fast_ex2(q4.x * fast_lg2(z2 * q3.z));

            const float A  = t1 + t2 + EPS_F;
            const float B  = fast_ex2(q4.y * fast_lg2(A)) + t3;
            const float f  = fast_ex2(q4.z * fast_lg2(B));

            float s = fmaf(-r0, f, r0);
            s = fminf(fmaxf(s, -TRUNC), TRUNC);
            s = nearL ? s : TRUNC;   // far lanes: provably exactly 0.1 (warp-independent)

            const bool upd = s < best;
            best = upd ? s : best;
            bi   = upd ? i : bi;
        }
    }

    if (p >= P) return;

    // ---- Pass 2: gradient for the single winning prim ----
    {
        const float4 q0 = sp[bi*PQ+0];
        const float4 q1 = sp[bi*PQ+1];
        const float4 q2 = sp[bi*PQ+2];
        const float4 q3 = sp[bi*PQ+3];
        const float4 q4 = sp[bi*PQ+4];

        const float xc = q0.x*px + q1.x*py + q2.x*pz - q0.w;
        const float yc = q0.y*px + q1.y*py + q2.y*pz - q1.w;
        const float zc = q0.z*px + q1.z*py + q2.z*pz - q2.w;

        const float axv = fabsf(xc), ayv = fabsf(yc), azv = fabsf(zc);
        const bool mx = axv > EPS_F, my = ayv > EPS_F, mz = azv > EPS_F;
        const float X = copysignf(fmaxf(axv, EPS_F), xc);
        const float Y = copysignf(fmaxf(ayv, EPS_F), yc);
        const float Z = copysignf(fmaxf(azv, EPS_F), zc);

        const float x2 = X*X, y2 = Y*Y, z2 = Z*Z;
        const float r2  = x2 + y2 + z2;
        const float ir0 = rsqrtf(r2);
        const float r0  = r2 * ir0;

        const float t1 = fast_ex2(q3.w * fast_lg2(x2 * q3.x));
        const float t2 = fast_ex2(q3.w * fast_lg2(y2 * q3.y));
        const float t3 = fast_ex2(q4.x * fast_lg2(z2 * q3.z));

        const float A    = t1 + t2 + EPS_F;
        const float lA   = fast_lg2(A);
        const float aAp  = q4.y * lA;
        const float Apow = fast_ex2(aAp);
        const float C    = fast_ex2(aAp - lA);   // A^(e2/e1-1)
        const float B    = Apow + t3;
        const float lB   = fast_lg2(B);
        const float af   = q4.z * lB;
        const float f    = fast_ex2(af);
        const float D    = fast_ex2(af - lB);    // B^(-e1/2-1)

        const float omf = 1.0f - f;

        const float XY = X*Y, YZ = Y*Z, XZ = X*Z;
        const float rP = fast_rcp(XY * Z);
        const float iX = YZ * rP, iY = XZ * rP, iZ = XY * rP;

        const float su  = ir0 * omf;
        const float rD  = r0 * D;
        const float Kxy = rD * C;
        const float gx = mx ? fmaf(X, su, (Kxy * t1) * iX) : 0.0f;
        const float gy = my ? fmaf(Y, su, (Kxy * t2) * iY) : 0.0f;
        const float gz = mz ? fmaf(Z, su, (rD  * t3) * iZ) : 0.0f;

        const float gwx = q0.x*gx + q0.y*gy + q0.z*gz;
        const float gwy = q1.x*gx + q1.y*gy + q1.z*gz;
        const float gwz = q2.x*gx + q2.y*gy + q2.z*gz;

        const float gn  = sqrtf(gwx*gwx + gwy*gwy + gwz*gwz);
        const float inv = 1.0f / fmaxf(gn, 1e-12f);

        out[orig] = best;
        float* no = out + P;
        no[3*orig+0] = gwx * inv;
        no[3*orig+1] = gwy * inv;
        no[3*orig+2] = gwz * inv;
    }
}

extern "C" void kernel_launch(void* const* d_in, const int* in_sizes, int n_in,
                              void* d_out, int out_size)
{
    const float* raw_scale = (const float*)d_in[0];
    const float* raw_exp   = (const float*)d_in[1];
    const float* raw_rot   = (const float*)d_in[2];
    const float* trans     = (const float*)d_in[3];
    const float* points    = (const float*)d_in[4];
    float* out = (float*)d_out;

    int P = in_sizes[4] / 3;
    if (P > MAXP) P = MAXP;

    const int threads = 256;
    const int blocks  = (P + threads - 1) / threads;

    k_zero<<<(NCELL + 255) / 256, 256>>>();
    k_count<<<blocks, threads>>>(points, P);
    k_scan<<<1, 1024>>>();
    k_scatter<<<blocks, threads>>>(points, P);
    superq_kernel<<<blocks, threads>>>(raw_scale, raw_exp, raw_rot, trans, out, P);
}

// round 6
// speedup vs baseline: 1.8595x; 1.8595x over previous
#include <cuda_runtime.h>
#include <math.h>

#define NSQ    64
#define EPS_F  1e-6f
#define EPS2_F 1e-12f
#define TRUNC  0.1f

typedef unsigned long long pf2;

__device__ __forceinline__ pf2 pk(float a, float b){ pf2 r; asm("mov.b64 %0,{%1,%2};":"=l"(r):"f"(a),"f"(b)); return r; }
__device__ __forceinline__ void upk(pf2 v, float& a, float& b){ asm("mov.b64 {%0,%1},%2;":"=f"(a),"=f"(b):"l"(v)); }
__device__ __forceinline__ pf2 bc(float a){ pf2 r; asm("mov.b64 %0,{%1,%1};":"=l"(r):"f"(a)); return r; }
__device__ __forceinline__ pf2 f2fma(pf2 a, pf2 b, pf2 c){ pf2 r; asm("fma.rn.f32x2 %0,%1,%2,%3;":"=l"(r):"l"(a),"l"(b),"l"(c)); return r; }
__device__ __forceinline__ pf2 f2mul(pf2 a, pf2 b){ pf2 r; asm("mul.rn.f32x2 %0,%1,%2;":"=l"(r):"l"(a),"l"(b)); return r; }
__device__ __forceinline__ pf2 f2add(pf2 a, pf2 b){ pf2 r; asm("add.rn.f32x2 %0,%1,%2;":"=l"(r):"l"(a),"l"(b)); return r; }

__device__ __forceinline__ float fast_lg2(float x){ float r; asm("lg2.approx.f32 %0, %1;":"=f"(r):"f"(x)); return r; }
__device__ __forceinline__ float fast_ex2(float x){ float r; asm("ex2.approx.f32 %0, %1;":"=f"(r):"f"(x)); return r; }
__device__ __forceinline__ float fast_rcp(float x){ float r; asm("rcp.approx.f32 %0, %1;":"=f"(r):"f"(x)); return r; }
__device__ __forceinline__ float fast_sqrt(float x){ float r; asm("sqrt.approx.f32 %0, %1;":"=f"(r):"f"(x)); return r; }

// packed 2^u via Taylor deg-5 on the fractional part; integer-side exponent clamp.
__device__ __forceinline__ pf2 ex2p(pf2 u){
    const pf2 MAGIC = bc(12582912.0f);     // 1.5*2^23
    const pf2 NMAG  = bc(-12582912.0f);
    const pf2 NONE  = bc(-1.0f);
    const pf2 C5 = bc(1.333355815e-3f);
    const pf2 C4 = bc(9.618129107e-3f);
    const pf2 C3 = bc(5.550410866e-2f);
    const pf2 C2 = bc(2.402265070e-1f);
    const pf2 C1 = bc(6.931471806e-1f);
    const pf2 ONE = bc(1.0f);
    pf2 k = f2add(u, MAGIC);               // rounds u to nearest int (in mantissa)
    pf2 t = f2add(k, NMAG);                // t = n (exact)
    pf2 h = f2fma(t, NONE, u);             // h = u - n, in [-0.5, 0.5]
    pf2 p = f2fma(h, C5, C4);
    p = f2fma(h, p, C3);
    p = f2fma(h, p, C2);
    p = f2fma(h, p, C1);
    p = f2fma(h, p, ONE);                  // 2^h
    float k0, k1; upk(k, k0, k1);
    int e0 = (int)__float_as_uint(k0) - 0x4B3FFF81;   // n + 127
    int e1 = (int)__float_as_uint(k1) - 0x4B3FFF81;
    e0 = e0 < 1 ? 1 : (e0 > 253 ? 253 : e0);
    e1 = e1 < 1 ? 1 : (e1 > 253 ? 253 : e1);
    pf2 sc = pk(__uint_as_float((unsigned)e0 << 23), __uint_as_float((unsigned)e1 << 23));
    return f2mul(p, sc);
}

// param positions within a prim's 10 ulonglong2 slots (each holds 2 duplicated params)
// 0:r00 1:r01 2:r02 3:ntbx 4:r10 5:r11 6:r12 7:ntby 8:r20 9:r21 10:r22 11:ntbz
// 12:isx2 13:isy2 14:isz2 15:ie2 16:ie1 17:e21(e2/e1) 18:ne1h(-e1/2) 19:pad
#define PRM(fv, i, j) (fv)[(((i)*10 + ((j) >> 1)) << 2) + (((j) & 1) << 1)]

__device__ __forceinline__ void write_pt(const float* fv, int bi,
                                         float px, float py, float pz,
                                         float best, float* out, int P, int p)
{
    const float r00 = PRM(fv,bi,0),  r01 = PRM(fv,bi,1),  r02 = PRM(fv,bi,2);
    const float r10 = PRM(fv,bi,4),  r11 = PRM(fv,bi,5),  r12 = PRM(fv,bi,6);
    const float r20 = PRM(fv,bi,8),  r21 = PRM(fv,bi,9),  r22 = PRM(fv,bi,10);
    const float ntbx = PRM(fv,bi,3), ntby = PRM(fv,bi,7), ntbz = PRM(fv,bi,11);
    const float isx2 = PRM(fv,bi,12), isy2 = PRM(fv,bi,13), isz2 = PRM(fv,bi,14);
    const float ie2 = PRM(fv,bi,15), ie1 = PRM(fv,bi,16);
    const float e21 = PRM(fv,bi,17), ne1h = PRM(fv,bi,18);

    const float xc = r00*px + r10*py + r20*pz + ntbx;
    const float yc = r01*px + r11*py + r21*pz + ntby;
    const float zc = r02*px + r12*py + r22*pz + ntbz;

    const float axv = fabsf(xc), ayv = fabsf(yc), azv = fabsf(zc);
    const bool mx = axv > EPS_F, my = ayv > EPS_F, mz = azv > EPS_F;
    const float X = copysignf(fmaxf(axv, EPS_F), xc);
    const float Y = copysignf(fmaxf(ayv, EPS_F), yc);
    const float Z = copysignf(fmaxf(azv, EPS_F), zc);

    const float x2 = X*X, y2 = Y*Y, z2 = Z*Z;
    const float r2  = x2 + y2 + z2;
    const float ir0 = rsqrtf(r2);
    const float r0  = r2 * ir0;

    const float t1 = fast_ex2(ie2 * fast_lg2(x2 * isx2));
    const float t2 = fast_ex2(ie2 * fast_lg2(y2 * isy2));
    const float t3 = fast_ex2(ie1 * fast_lg2(z2 * isz2));

    const float A    = t1 + t2 + EPS_F;
    const float lA   = fast_lg2(A);
    const float aAp  = e21 * lA;
    const float Apow = fast_ex2(aAp);
    const float C    = fast_ex2(aAp - lA);   // A^(e2/e1-1)
    const float B    = Apow + t3;
    const float lB   = fast_lg2(B);
    const float af   = ne1h * lB;
    const float f    = fast_ex2(af);
    const float D    = fast_ex2(af - lB);    // B^(-e1/2-1)

    const float omf = 1.0f - f;

    const float XY = X*Y, YZ = Y*Z, XZ = X*Z;
    const float rP = fast_rcp(XY * Z);
    const float iX = YZ * rP, iY = XZ * rP, iZ = XY * rP;

    const float su  = ir0 * omf;
    const float rD  = r0 * D;
    const float Kxy = rD * C;
    const float gx = mx ? fmaf(X, su, (Kxy * t1) * iX) : 0.0f;
    const float gy = my ? fmaf(Y, su, (Kxy * t2) * iY) : 0.0f;
    const float gz = mz ? fmaf(Z, su, (rD  * t3) * iZ) : 0.0f;

    const float gwx = r00*gx + r01*gy + r02*gz;
    const float gwy = r10*gx + r11*gy + r12*gz;
    const float gwz = r20*gx + r21*gy + r22*gz;

    const float gn  = sqrtf(gwx*gwx + gwy*gwy + gwz*gwz);
    const float inv = 1.0f / fmaxf(gn, 1e-12f);

    out[p] = best;
    float* no = out + P;
    no[3*p+0] = gwx * inv;
    no[3*p+1] = gwy * inv;
    no[3*p+2] = gwz * inv;
}

__global__ void __launch_bounds__(256, 2)
superq_kernel(const float* __restrict__ raw_scale,
              const float* __restrict__ raw_exp,
              const float* __restrict__ raw_rot,
              const float* __restrict__ trans,
              const float* __restrict__ points,
              float* __restrict__ out,
              int P)
{
    __shared__ ulonglong2 spp[NSQ * 10];
    const int tid = threadIdx.x;

    if (tid < NSQ) {
        const int i = tid;
        float qw = raw_rot[4*i+0], qx = raw_rot[4*i+1];
        float qy = raw_rot[4*i+2], qz = raw_rot[4*i+3];
        float qn = 1.0f / sqrtf(qw*qw + qx*qx + qy*qy + qz*qz);
        qw *= qn; qx *= qn; qy *= qn; qz *= qn;
        const float r00 = 1.0f - 2.0f*(qy*qy + qz*qz);
        const float r01 = 2.0f*(qx*qy - qw*qz);
        const float r02 = 2.0f*(qx*qz + qw*qy);
        const float r10 = 2.0f*(qx*qy + qw*qz);
        const float r11 = 1.0f - 2.0f*(qx*qx + qz*qz);
        const float r12 = 2.0f*(qy*qz - qw*qx);
        const float r20 = 2.0f*(qx*qz - qw*qy);
        const float r21 = 2.0f*(qy*qz + qw*qx);
        const float r22 = 1.0f - 2.0f*(qx*qx + qy*qy);
        const float tx = trans[3*i+0], ty = trans[3*i+1], tz = trans[3*i+2];
        const float ntbx = -(r00*tx + r10*ty + r20*tz);
        const float ntby = -(r01*tx + r11*ty + r21*tz);
        const float ntbz = -(r02*tx + r12*ty + r22*tz);
        const float isx2 = expf(-2.0f * raw_scale[3*i+0]);
        const float isy2 = expf(-2.0f * raw_scale[3*i+1]);
        const float isz2 = expf(-2.0f * raw_scale[3*i+2]);
        const float e1 = 0.1f + 1.8f / (1.0f + expf(-raw_exp[2*i+0]));
        const float e2 = 0.1f + 1.8f / (1.0f + expf(-raw_exp[2*i+1]));

        float2* f2v = (float2*)spp;
        const float prm[20] = { r00, r01, r02, ntbx, r10, r11, r12, ntby,
                                r20, r21, r22, ntbz, isx2, isy2, isz2, 1.0f/e2,
                                1.0f/e1, e2/e1, -0.5f*e1, 0.0f };
        #pragma unroll
        for (int j = 0; j < 20; j++)
            f2v[(i*10 + (j>>1))*2 + (j&1)] = make_float2(prm[j], prm[j]);
    }
    __syncthreads();

    const int g  = blockIdx.x * blockDim.x + tid;
    const int p0 = 2*g;
    if (p0 >= P) return;
    const int p1 = (p0 + 1 < P) ? p0 + 1 : p0;

    // load two points (coalesced float2s)
    const float2* pv = (const float2*)points;
    const float2 fa = pv[3*g+0];
    const float2 fb = pv[3*g+1];
    const float2 fc = pv[3*g+2];
    const float px0 = fa.x, py0 = fa.y, pz0 = fb.x;
    const float px1 = fb.y, py1 = fc.x, pz1 = fc.y;

    const pf2 pxp = pk(px0, px1);
    const pf2 pyp = pk(py0, py1);
    const pf2 pzp = pk(pz0, pz1);

    const pf2 EPS2P = bc(EPS2_F);
    const pf2 EPSP  = bc(EPS_F);
    const pf2 NONEP = bc(-1.0f);

    float best0 = 3.0e38f, best1 = 3.0e38f;
    int bi0 = 0, bi1 = 0;

#pragma unroll 1
    for (int i = 0; i < NSQ; i++) {
        const ulonglong2* pp = spp + i*10;
        const ulonglong2 L0 = pp[0], L1 = pp[1], L2 = pp[2], L3 = pp[3], L4 = pp[4];
        const ulonglong2 L5 = pp[5], L6 = pp[6], L7 = pp[7], L8 = pp[8], L9 = pp[9];

        // Xc = R^T p - R^T t   (ntb already negated)
        const pf2 xc = f2fma(L0.x, pxp, f2fma(L2.x, pyp, f2fma(L4.x, pzp, L1.y)));
        const pf2 yc = f2fma(L0.y, pxp, f2fma(L2.y, pyp, f2fma(L4.y, pzp, L3.y)));
        const pf2 zc = f2fma(L1.x, pxp, f2fma(L3.x, pyp, f2fma(L5.x, pzp, L5.y)));

        const pf2 x2 = f2fma(xc, xc, EPS2P);
        const pf2 y2 = f2fma(yc, yc, EPS2P);
        const pf2 z2 = f2fma(zc, zc, EPS2P);

        const pf2 r2 = f2add(f2add(x2, y2), z2);
        float r2a, r2b; upk(r2, r2a, r2b);
        const pf2 r0p = pk(fast_sqrt(r2a), fast_sqrt(r2b));

        const pf2 ax = f2mul(x2, L6.x);
        const pf2 ay = f2mul(y2, L6.y);
        const pf2 az = f2mul(z2, L7.x);
        float a0, a1, b0, b1, c0, c1;
        upk(ax, a0, a1); upk(ay, b0, b1); upk(az, c0, c1);
        const pf2 lxp = pk(fast_lg2(a0), fast_lg2(a1));
        const pf2 lyp = pk(fast_lg2(b0), fast_lg2(b1));
        const pf2 lzp = pk(fast_lg2(c0), fast_lg2(c1));

        const pf2 t1 = ex2p(f2mul(lxp, L7.y));   // (x^2/sx^2)^(1/e2)
        const pf2 t2 = ex2p(f2mul(lyp, L7.y));
        const pf2 t3 = ex2p(f2mul(lzp, L8.x));   // (z^2/sz^2)^(1/e1)

        const pf2 A = f2add(f2add(t1, t2), EPSP);
        float A0, A1; upk(A, A0, A1);
        float e21s, du; upk(L8.y, e21s, du);
        const float Ap0 = fast_ex2(e21s * fast_lg2(A0));
        const float Ap1 = fast_ex2(e21s * fast_lg2(A1));
        const pf2 B = f2add(pk(Ap0, Ap1), t3);
        float B0, B1; upk(B, B0, B1);
        float ne1hs, dv; upk(L9.x, ne1hs, dv);
        const float f0 = fast_ex2(ne1hs * fast_lg2(B0));
        const float f1 = fast_ex2(ne1hs * fast_lg2(B1));

        const pf2 m = f2mul(r0p, pk(f0, f1));
        const pf2 s = f2fma(m, NONEP, r0p);      // r0*(1-f)
        float s0, s1; upk(s, s0, s1);
        s0 = fminf(fmaxf(s0, -TRUNC), TRUNC);
        s1 = fminf(fmaxf(s1, -TRUNC), TRUNC);

        if (s0 < best0) { best0 = s0; bi0 = i; }
        if (s1 < best1) { best1 = s1; bi1 = i; }
    }

    const float* fv = (const float*)spp;
    write_pt(fv, bi0, px0, py0, pz0, best0, out, P, p0);
    if (p0 + 1 < P)
        write_pt(fv, bi1, px1, py1, pz1, best1, out, P, p1);
}

extern "C" void kernel_launch(void* const* d_in, const int* in_sizes, int n_in,
                              void* d_out, int out_size)
{
    const float* raw_scale = (const float*)d_in[0];
    const float* raw_exp   = (const float*)d_in[1];
    const float* raw_rot   = (const float*)d_in[2];
    const float* trans     = (const float*)d_in[3];
    const float* points    = (const float*)d_in[4];
    float* out = (float*)d_out;

    const int P = in_sizes[4] / 3;
    const int threads = 256;
    const int pairs   = (P + 1) / 2;
    const int blocks  = (pairs + threads - 1) / threads;
    superq_kernel<<<blocks, threads>>>(raw_scale, raw_exp, raw_rot, trans,
                                       points, out, P);
}

// round 7
// speedup vs baseline: 2.2690x; 1.2202x over previous
#include <cuda_runtime.h>
#include <math.h>

#define NSQ    64
#define EPS_F  1e-6f
#define EPS2_F 1e-12f
#define TRUNC  0.1f

typedef unsigned long long pf2;

__device__ __forceinline__ pf2 pk(float a, float b){ pf2 r; asm("mov.b64 %0,{%1,%2};":"=l"(r):"f"(a),"f"(b)); return r; }
__device__ __forceinline__ void upk(pf2 v, float& a, float& b){ asm("mov.b64 {%0,%1},%2;":"=f"(a),"=f"(b):"l"(v)); }
__device__ __forceinline__ pf2 bc2(float a){ pf2 r; asm("mov.b64 %0,{%1,%1};":"=l"(r):"f"(a)); return r; }
__device__ __forceinline__ pf2 f2fma(pf2 a, pf2 b, pf2 c){ pf2 r; asm("fma.rn.f32x2 %0,%1,%2,%3;":"=l"(r):"l"(a),"l"(b),"l"(c)); return r; }
__device__ __forceinline__ pf2 f2mul(pf2 a, pf2 b){ pf2 r; asm("mul.rn.f32x2 %0,%1,%2;":"=l"(r):"l"(a),"l"(b)); return r; }
__device__ __forceinline__ pf2 f2add(pf2 a, pf2 b){ pf2 r; asm("add.rn.f32x2 %0,%1,%2;":"=l"(r):"l"(a),"l"(b)); return r; }

__device__ __forceinline__ float fast_lg2(float x){ float r; asm("lg2.approx.f32 %0, %1;":"=f"(r):"f"(x)); return r; }
__device__ __forceinline__ float fast_ex2(float x){ float r; asm("ex2.approx.f32 %0, %1;":"=f"(r):"f"(x)); return r; }
__device__ __forceinline__ float fast_rcp(float x){ float r; asm("rcp.approx.f32 %0, %1;":"=f"(r):"f"(x)); return r; }
__device__ __forceinline__ float fast_sqrt(float x){ float r; asm("sqrt.approx.f32 %0, %1;":"=f"(r):"f"(x)); return r; }

// packed 2^u for two independent args; deg-5 Taylor on fractional part,
// integer-side biased-exponent clamp to [2^-126, 2^126]. |u| < ~4e6 ok.
__device__ __forceinline__ void ex2_pair(float u0f, float u1f, float& o0, float& o1){
    const pf2 MAGIC = bc2(12582912.0f);     // 1.5*2^23
    const pf2 NMAG  = bc2(-12582912.0f);
    const pf2 NONE  = bc2(-1.0f);
    const pf2 C5 = bc2(1.333355815e-3f);
    const pf2 C4 = bc2(9.618129107e-3f);
    const pf2 C3 = bc2(5.550410866e-2f);
    const pf2 C2 = bc2(2.402265070e-1f);
    const pf2 C1 = bc2(6.931471806e-1f);
    const pf2 ONE = bc2(1.0f);
    pf2 u = pk(u0f, u1f);
    pf2 k = f2add(u, MAGIC);               // round-to-nearest int in mantissa
    pf2 t = f2add(k, NMAG);                // t = n (exact float)
    pf2 h = f2fma(t, NONE, u);             // h = u - n in [-0.5,0.5]
    pf2 p = f2fma(h, C5, C4);
    p = f2fma(h, p, C3);
    p = f2fma(h, p, C2);
    p = f2fma(h, p, C1);
    p = f2fma(h, p, ONE);                  // 2^h
    float k0, k1; upk(k, k0, k1);
    int e0 = (int)__float_as_uint(k0) - 0x4B3FFF81;   // n + 127
    int e1 = (int)__float_as_uint(k1) - 0x4B3FFF81;
    e0 = e0 < 1 ? 1 : (e0 > 253 ? 253 : e0);
    e1 = e1 < 1 ? 1 : (e1 > 253 ? 253 : e1);
    pf2 sc = pk(__uint_as_float((unsigned)e0 << 23), __uint_as_float((unsigned)e1 << 23));
    pf2 r = f2mul(p, sc);
    upk(r, o0, o1);
}

// 5 float4 per prim:
// q0 = {r00,r01,r02, ntbx}   ntb = -(R^T t)
// q1 = {r10,r11,r12, ntby}
// q2 = {r20,r21,r22, ntbz}
// q3 = {K1,K2,K3, ie2}       Kj = iej-coef * log2(1/s_j^2)
// q4 = {ie1, e21(e2/e1), ne1h(-e1/2), pad}
#define PQ 5

__global__ void __launch_bounds__(256, 4)
superq_kernel(const float* __restrict__ raw_scale,
              const float* __restrict__ raw_exp,
              const float* __restrict__ raw_rot,
              const float* __restrict__ trans,
              const float* __restrict__ points,
              float* __restrict__ out,
              int P)
{
    __shared__ float4 sp[NSQ * PQ];
    const int tid = threadIdx.x;

    if (tid < NSQ) {
        const int i = tid;
        float qw = raw_rot[4*i+0], qx = raw_rot[4*i+1];
        float qy = raw_rot[4*i+2], qz = raw_rot[4*i+3];
        float qn = 1.0f / sqrtf(qw*qw + qx*qx + qy*qy + qz*qz);
        qw *= qn; qx *= qn; qy *= qn; qz *= qn;
        const float r00 = 1.0f - 2.0f*(qy*qy + qz*qz);
        const float r01 = 2.0f*(qx*qy - qw*qz);
        const float r02 = 2.0f*(qx*qz + qw*qy);
        const float r10 = 2.0f*(qx*qy + qw*qz);
        const float r11 = 1.0f - 2.0f*(qx*qx + qz*qz);
        const float r12 = 2.0f*(qy*qz - qw*qx);
        const float r20 = 2.0f*(qx*qz - qw*qy);
        const float r21 = 2.0f*(qy*qz + qw*qx);
        const float r22 = 1.0f - 2.0f*(qx*qx + qy*qy);
        const float tx = trans[3*i+0], ty = trans[3*i+1], tz = trans[3*i+2];
        const float ntbx = -(r00*tx + r10*ty + r20*tz);
        const float ntby = -(r01*tx + r11*ty + r21*tz);
        const float ntbz = -(r02*tx + r12*ty + r22*tz);
        const float e1 = 0.1f + 1.8f / (1.0f + expf(-raw_exp[2*i+0]));
        const float e2 = 0.1f + 1.8f / (1.0f + expf(-raw_exp[2*i+1]));
        const float ie1 = 1.0f/e1, ie2 = 1.0f/e2;
        // log2(1/s^2) = -2*raw_scale/ln(2)
        const float L2E = 1.4426950408889634f;
        const float Lx = -2.0f * raw_scale[3*i+0] * L2E;
        const float Ly = -2.0f * raw_scale[3*i+1] * L2E;
        const float Lz = -2.0f * raw_scale[3*i+2] * L2E;
        sp[i*PQ+0] = make_float4(r00, r01, r02, ntbx);
        sp[i*PQ+1] = make_float4(r10, r11, r12, ntby);
        sp[i*PQ+2] = make_float4(r20, r21, r22, ntbz);
        sp[i*PQ+3] = make_float4(ie2*Lx, ie2*Ly, ie1*Lz, ie2);
        sp[i*PQ+4] = make_float4(ie1, e2/e1, -0.5f*e1, 0.0f);
    }
    __syncthreads();

    const int p = blockIdx.x * blockDim.x + tid;
    if (p >= P) return;

    const float px = points[3*p+0];
    const float py = points[3*p+1];
    const float pz = points[3*p+2];

    float best = TRUNC;   // upper clamp folded into the init (strict-< keeps first-min)
    int   bi   = 0;

    // ---- Pass 1: sdf-only argmin ----
#pragma unroll 4
    for (int i = 0; i < NSQ; i++) {
        const float4 q0 = sp[i*PQ+0];
        const float4 q1 = sp[i*PQ+1];
        const float4 q2 = sp[i*PQ+2];
        const float4 q3 = sp[i*PQ+3];
        const float4 q4 = sp[i*PQ+4];

        const float xc = q0.x*px + q1.x*py + q2.x*pz + q0.w;
        const float yc = q0.y*px + q1.y*py + q2.y*pz + q1.w;
        const float zc = q0.z*px + q1.z*py + q2.z*pz + q2.w;

        const float x2 = fmaxf(xc*xc, EPS2_F);
        const float y2 = fmaxf(yc*yc, EPS2_F);
        const float z2 = fmaxf(zc*zc, EPS2_F);

        const float r2 = x2 + y2 + z2;
        const float r0 = fast_sqrt(r2);

        // u = ie * (lg2(x2) + lg2(1/s^2)) folded: fma(ie, lg2(x2), K)
        const float u1 = fmaf(q3.w, fast_lg2(x2), q3.x);
        const float u2 = fmaf(q3.w, fast_lg2(y2), q3.y);
        const float u3 = fmaf(q4.x, fast_lg2(z2), q3.z);

        float t1, t2;
        ex2_pair(u1, u2, t1, t2);          // FMA-pipe poly (2 MUFU saved)
        const float t3 = fast_ex2(u3);

        const float A = t1 + t2 + EPS_F;
        const float B = fast_ex2(q4.y * fast_lg2(A)) + t3;
        const float f = fast_ex2(q4.z * fast_lg2(B));

        float s = fmaf(-f, r0, r0);        // r0*(1-f)
        s = fmaxf(s, -TRUNC);              // lower clamp only

        if (s < best) { best = s; bi = i; }
    }

    // ---- Pass 2: gradient for the single winning prim ----
    {
        const float4 q0 = sp[bi*PQ+0];
        const float4 q1 = sp[bi*PQ+1];
        const float4 q2 = sp[bi*PQ+2];
        const float4 q3 = sp[bi*PQ+3];
        const float4 q4 = sp[bi*PQ+4];

        const float xc = q0.x*px + q1.x*py + q2.x*pz + q0.w;
        const float yc = q0.y*px + q1.y*py + q2.y*pz + q1.w;
        const float zc = q0.z*px + q1.z*py + q2.z*pz + q2.w;

        const float axv = fabsf(xc), ayv = fabsf(yc), azv = fabsf(zc);
        const bool mx = axv > EPS_F, my = ayv > EPS_F, mz = azv > EPS_F;
        const float X = copysignf(fmaxf(axv, EPS_F), xc);
        const float Y = copysignf(fmaxf(ayv, EPS_F), yc);
        const float Z = copysignf(fmaxf(azv, EPS_F), zc);

        const float x2 = X*X, y2 = Y*Y, z2 = Z*Z;
        const float r2  = x2 + y2 + z2;
        const float ir0 = rsqrtf(r2);
        const float r0  = r2 * ir0;

        const float t1 = fast_ex2(fmaf(q3.w, fast_lg2(x2), q3.x));
        const float t2 = fast_ex2(fmaf(q3.w, fast_lg2(y2), q3.y));
        const float t3 = fast_ex2(fmaf(q4.x, fast_lg2(z2), q3.z));

        const float A    = t1 + t2 + EPS_F;
        const float lA   = fast_lg2(A);
        const float aAp  = q4.y * lA;
        const float Apow = fast_ex2(aAp);
        const float C    = fast_ex2(aAp - lA);   // A^(e2/e1-1)
        const float B    = Apow + t3;
        const float lB   = fast_lg2(B);
        const float af   = q4.z * lB;
        const float f    = fast_ex2(af);
        const float D    = fast_ex2(af - lB);    // B^(-e1/2-1)

        const float omf = 1.0f - f;

        const float XY = X*Y, YZ = Y*Z, XZ = X*Z;
        const float rP = fast_rcp(XY * Z);
        const float iX = YZ * rP, iY = XZ * rP, iZ = XY * rP;

        const float su  = ir0 * omf;
        const float rD  = r0 * D;
        const float Kxy = rD * C;
        const float gx = mx ? fmaf(X, su, (Kxy * t1) * iX) : 0.0f;
        const float gy = my ? fmaf(Y, su, (Kxy * t2) * iY) : 0.0f;
        const float gz = mz ? fmaf(Z, su, (rD  * t3) * iZ) : 0.0f;

        const float gwx = q0.x*gx + q0.y*gy + q0.z*gz;
        const float gwy = q1.x*gx + q1.y*gy + q1.z*gz;
        const float gwz = q2.x*gx + q2.y*gy + q2.z*gz;

        const float gn  = sqrtf(gwx*gwx + gwy*gwy + gwz*gwz);
        const float inv = 1.0f / fmaxf(gn, 1e-12f);

        out[p] = best;
        float* no = out + P;
        no[3*p+0] = gwx * inv;
        no[3*p+1] = gwy * inv;
        no[3*p+2] = gwz * inv;
    }
}

extern "C" void kernel_launch(void* const* d_in, const int* in_sizes, int n_in,
                              void* d_out, int out_size)
{
    const float* raw_scale = (const float*)d_in[0];
    const float* raw_exp   = (const float*)d_in[1];
    const float* raw_rot   = (const float*)d_in[2];
    const float* trans     = (const float*)d_in[3];
    const float* points    = (const float*)d_in[4];
    float* out = (float*)d_out;

    const int P = in_sizes[4] / 3;
    const int threads = 256;
    const int blocks  = (P + threads - 1) / threads;
    superq_kernel<<<blocks, threads>>>(raw_scale, raw_exp, raw_rot, trans,
                                       points, out, P);
}

// round 8
// speedup vs baseline: 2.6770x; 1.1798x over previous
#include <cuda_runtime.h>
#include <math.h>

#define NSQ    64
#define EPS_F  1e-6f
#define EPS2_F 1e-12f
#define TRUNC  0.1f

__device__ __forceinline__ float fast_lg2(float x){ float r; asm("lg2.approx.f32 %0, %1;":"=f"(r):"f"(x)); return r; }
__device__ __forceinline__ float fast_ex2(float x){ float r; asm("ex2.approx.f32 %0, %1;":"=f"(r):"f"(x)); return r; }
__device__ __forceinline__ float fast_rcp(float x){ float r; asm("rcp.approx.f32 %0, %1;":"=f"(r):"f"(x)); return r; }
__device__ __forceinline__ float fast_sqrt(float x){ float r; asm("sqrt.approx.f32 %0, %1;":"=f"(r):"f"(x)); return r; }

// 5 float4 per prim:
// q0 = {r00,r01,r02, ntbx}   ntb = -(R^T t)
// q1 = {r10,r11,r12, ntby}
// q2 = {r20,r21,r22, ntbz}
// q3 = {K1,K2,K3, ie2}       K1 = ie2*log2(1/sx^2), K2 = ie2*log2(1/sy^2), K3 = ie1*log2(1/sz^2)
// q4 = {ie1, e21(e2/e1), ne1h(-e1/2), pad}
#define PQ 5

__global__ void __launch_bounds__(128, 8)
superq_kernel(const float* __restrict__ raw_scale,
              const float* __restrict__ raw_exp,
              const float* __restrict__ raw_rot,
              const float* __restrict__ trans,
              const float* __restrict__ points,
              float* __restrict__ out,
              int P)
{
    __shared__ float4 sp[NSQ * PQ];
    const int tid = threadIdx.x;

    if (tid < NSQ) {
        const int i = tid;
        float qw = raw_rot[4*i+0], qx = raw_rot[4*i+1];
        float qy = raw_rot[4*i+2], qz = raw_rot[4*i+3];
        float qn = 1.0f / sqrtf(qw*qw + qx*qx + qy*qy + qz*qz);
        qw *= qn; qx *= qn; qy *= qn; qz *= qn;
        const float r00 = 1.0f - 2.0f*(qy*qy + qz*qz);
        const float r01 = 2.0f*(qx*qy - qw*qz);
        const float r02 = 2.0f*(qx*qz + qw*qy);
        const float r10 = 2.0f*(qx*qy + qw*qz);
        const float r11 = 1.0f - 2.0f*(qx*qx + qz*qz);
        const float r12 = 2.0f*(qy*qz - qw*qx);
        const float r20 = 2.0f*(qx*qz - qw*qy);
        const float r21 = 2.0f*(qy*qz + qw*qx);
        const float r22 = 1.0f - 2.0f*(qx*qx + qy*qy);
        const float tx = trans[3*i+0], ty = trans[3*i+1], tz = trans[3*i+2];
        const float ntbx = -(r00*tx + r10*ty + r20*tz);
        const float ntby = -(r01*tx + r11*ty + r21*tz);
        const float ntbz = -(r02*tx + r12*ty + r22*tz);
        const float e1 = 0.1f + 1.8f / (1.0f + expf(-raw_exp[2*i+0]));
        const float e2 = 0.1f + 1.8f / (1.0f + expf(-raw_exp[2*i+1]));
        const float ie1 = 1.0f/e1, ie2 = 1.0f/e2;
        const float L2E = 1.4426950408889634f;   // log2(e)
        const float Lx = -2.0f * raw_scale[3*i+0] * L2E;   // log2(1/sx^2)
        const float Ly = -2.0f * raw_scale[3*i+1] * L2E;
        const float Lz = -2.0f * raw_scale[3*i+2] * L2E;
        sp[i*PQ+0] = make_float4(r00, r01, r02, ntbx);
        sp[i*PQ+1] = make_float4(r10, r11, r12, ntby);
        sp[i*PQ+2] = make_float4(r20, r21, r22, ntbz);
        sp[i*PQ+3] = make_float4(ie2*Lx, ie2*Ly, ie1*Lz, ie2);
        sp[i*PQ+4] = make_float4(ie1, e2/e1, -0.5f*e1, 0.0f);
    }
    __syncthreads();

    const int p = blockIdx.x * blockDim.x + tid;
    if (p >= P) return;

    const float px = points[3*p+0];
    const float py = points[3*p+1];
    const float pz = points[3*p+2];

    float best = TRUNC;   // upper clamp folded into init; strict-< keeps first-min
    int   bi   = 0;

    // ---- Pass 1: sdf-only argmin ----
#pragma unroll 4
    for (int i = 0; i < NSQ; i++) {
        const float4 q0 = sp[i*PQ+0];
        const float4 q1 = sp[i*PQ+1];
        const float4 q2 = sp[i*PQ+2];
        const float4 q3 = sp[i*PQ+3];
        const float4 q4 = sp[i*PQ+4];

        const float xc = q0.x*px + q1.x*py + q2.x*pz + q0.w;
        const float yc = q0.y*px + q1.y*py + q2.y*pz + q1.w;
        const float zc = q0.z*px + q1.z*py + q2.z*pz + q2.w;

        // x2 ~= max(xc^2, eps^2): fused add form (validated R6, same rel_err)
        const float x2 = fmaf(xc, xc, EPS2_F);
        const float y2 = fmaf(yc, yc, EPS2_F);
        const float z2 = fmaf(zc, zc, EPS2_F);

        const float r2 = x2 + y2 + z2;
        const float r0 = fast_sqrt(r2);

        // u = ie*lg2(x^2) + ie*log2(1/s^2)  (scale folded into constant)
        const float t1 = fast_ex2(fmaf(q3.w, fast_lg2(x2), q3.x));
        const float t2 = fast_ex2(fmaf(q3.w, fast_lg2(y2), q3.y));
        const float t3 = fast_ex2(fmaf(q4.x, fast_lg2(z2), q3.z));

        const float A = t1 + t2 + EPS_F;
        const float B = fast_ex2(q4.y * fast_lg2(A)) + t3;
        const float f = fast_ex2(q4.z * fast_lg2(B));

        float s = fmaf(-f, r0, r0);        // r0*(1-f)
        s = fmaxf(s, -TRUNC);              // lower clamp only

        if (s < best) { best = s; bi = i; }
    }

    // ---- Pass 2: exact-form gradient + sdf path for the winning prim ----
    {
        const float4 q0 = sp[bi*PQ+0];
        const float4 q1 = sp[bi*PQ+1];
        const float4 q2 = sp[bi*PQ+2];
        const float4 q3 = sp[bi*PQ+3];
        const float4 q4 = sp[bi*PQ+4];

        const float xc = q0.x*px + q1.x*py + q2.x*pz + q0.w;
        const float yc = q0.y*px + q1.y*py + q2.y*pz + q1.w;
        const float zc = q0.z*px + q1.z*py + q2.z*pz + q2.w;

        const float axv = fabsf(xc), ayv = fabsf(yc), azv = fabsf(zc);
        const bool mx = axv > EPS_F, my = ayv > EPS_F, mz = azv > EPS_F;
        const float X = copysignf(fmaxf(axv, EPS_F), xc);
        const float Y = copysignf(fmaxf(ayv, EPS_F), yc);
        const float Z = copysignf(fmaxf(azv, EPS_F), zc);

        const float x2 = X*X, y2 = Y*Y, z2 = Z*Z;
        const float r2  = x2 + y2 + z2;
        const float ir0 = rsqrtf(r2);
        const float r0  = r2 * ir0;

        const float t1 = fast_ex2(fmaf(q3.w, fast_lg2(x2), q3.x));
        const float t2 = fast_ex2(fmaf(q3.w, fast_lg2(y2), q3.y));
        const float t3 = fast_ex2(fmaf(q4.x, fast_lg2(z2), q3.z));

        const float A    = t1 + t2 + EPS_F;
        const float lA   = fast_lg2(A);
        const float aAp  = q4.y * lA;
        const float Apow = fast_ex2(aAp);
        const float C    = fast_ex2(aAp - lA);   // A^(e2/e1-1)
        const float B    = Apow + t3;
        const float lB   = fast_lg2(B);
        const float af   = q4.z * lB;
        const float f    = fast_ex2(af);
        const float D    = fast_ex2(af - lB);    // B^(-e1/2-1)

        const float omf = 1.0f - f;

        const float XY = X*Y, YZ = Y*Z, XZ = X*Z;
        const float rP = fast_rcp(XY * Z);
        const float iX = YZ * rP, iY = XZ * rP, iZ = XY * rP;

        const float su  = ir0 * omf;
        const float rD  = r0 * D;
        const float Kxy = rD * C;
        const float gx = mx ? fmaf(X, su, (Kxy * t1) * iX) : 0.0f;
        const float gy = my ? fmaf(Y, su, (Kxy * t2) * iY) : 0.0f;
        const float gz = mz ? fmaf(Z, su, (rD  * t3) * iZ) : 0.0f;

        const float gwx = q0.x*gx + q0.y*gy + q0.z*gz;
        const float gwy = q1.x*gx + q1.y*gy + q1.z*gz;
        const float gwz = q2.x*gx + q2.y*gy + q2.z*gz;

        const float gn  = sqrtf(gwx*gwx + gwy*gwy + gwz*gwz);
        const float inv = 1.0f / fmaxf(gn, 1e-12f);

        out[p] = best;
        float* no = out + P;
        no[3*p+0] = gwx * inv;
        no[3*p+1] = gwy * inv;
        no[3*p+2] = gwz * inv;
    }
}

extern "C" void kernel_launch(void* const* d_in, const int* in_sizes, int n_in,
                              void* d_out, int out_size)
{
    const float* raw_scale = (const float*)d_in[0];
    const float* raw_exp   = (const float*)d_in[1];
    const float* raw_rot   = (const float*)d_in[2];
    const float* trans     = (const float*)d_in[3];
    const float* points    = (const float*)d_in[4];
    float* out = (float*)d_out;

    const int P = in_sizes[4] / 3;
    const int threads = 128;
    const int blocks  = (P + threads - 1) / threads;
    superq_kernel<<<blocks, threads>>>(raw_scale, raw_exp, raw_rot, trans,
                                       points, out, P);
}